// round 7
// baseline (speedup 1.0000x reference)
#include <cuda_runtime.h>
#include <cstdint>

#define NUM_NODES 500000
#define D 128
#define U 32
#define T 4
#define A 32
#define N_SRC 65536
#define B 8192
#define E 262144
#define BB 16  // batch rows per finalize block

typedef unsigned long long ull;

// Packed f32x2 helpers (Blackwell FFMA2 path — PTX-only)
#define FMA_F32X2(d, a, b, c) \
    asm("fma.rn.f32x2 %0, %1, %2, %3;" : "=l"(d) : "l"(a), "l"(b), "l"(c))
#define PACK_DUP_F32X2(d, s) \
    asm("mov.b64 %0, {%1, %1};" : "=l"(d) : "f"(s))

// Scratch accumulator: agg[b][t][u]  (B*T*U floats = 4 MB)
__device__ float g_agg[B * T * U];

// ---------------------------------------------------------------------------
// Kernel 1: edge aggregation with vectorized global reductions.
// 8 lanes per edge, 2 edges per thread (independent chains for MLP).
// ---------------------------------------------------------------------------
__global__ __launch_bounds__(256) void edge_agg_kernel(
    const float* __restrict__ nte_tab,
    const int* __restrict__ input_nodes,
    const int* __restrict__ edge_src,
    const int* __restrict__ edge_dst) {
    const int t   = blockIdx.y;
    const int e0  = blockIdx.x * 64 + (threadIdx.x >> 3);   // 64 edges / block
    const int e1  = e0 + 32;
    const int sub = threadIdx.x & 7;                        // float4 slot in row

    const int src0 = __ldg(&edge_src[t * E + e0]);
    const int src1 = __ldg(&edge_src[t * E + e1]);
    const int dst0 = __ldg(&edge_dst[t * E + e0]);
    const int dst1 = __ldg(&edge_dst[t * E + e1]);
    const int n0   = __ldg(&input_nodes[src0]);
    const int n1   = __ldg(&input_nodes[src1]);

    const float4 v0 = __ldg((const float4*)nte_tab + (size_t)(n0 * T + t) * (U / 4) + sub);
    const float4 v1 = __ldg((const float4*)nte_tab + (size_t)(n1 * T + t) * (U / 4) + sub);

    float* p0 = g_agg + ((size_t)dst0 * T + t) * U + sub * 4;
    float* p1 = g_agg + ((size_t)dst1 * T + t) * U + sub * 4;
    asm volatile("red.global.add.v4.f32 [%0], {%1,%2,%3,%4};"
                 :: "l"(p0), "f"(v0.x), "f"(v0.y), "f"(v0.z), "f"(v0.w) : "memory");
    asm volatile("red.global.add.v4.f32 [%0], {%1,%2,%3,%4};"
                 :: "l"(p1), "f"(v1.x), "f"(v1.y), "f"(v1.z), "f"(v1.w) : "memory");
}

// ---------------------------------------------------------------------------
// Kernel 2: attention + combine + trans GEMM + residual + L2-normalize.
// BB=16 rows/block, 256 threads. Warp w: t = w&3, 8 rows. Packed f32x2 FMAs
// halve FMA-pipe pressure; LDS.128 for all shared reads.
// ---------------------------------------------------------------------------
__global__ __launch_bounds__(256, 4) void finalize_kernel(
    const float* __restrict__ node_emb,     // [NUM_NODES][D]
    const float* __restrict__ w,            // [T][U][D]
    const float* __restrict__ ws1,          // [T][U][A]
    const float* __restrict__ ws2,          // [T][A]
    const int*  __restrict__ out_nodes,     // [B]
    float*      __restrict__ out)           // [B][T][D]
{
    __shared__ float nte_s[BB][T * U];      // 8 KB
    __shared__ float scores_s[BB][T];
    __shared__ float att_s[BB][T];
    __shared__ float comb_s[BB][U];         // 2 KB

    const int b0   = blockIdx.x * BB;
    const int tid  = threadIdx.x;
    const int lane = tid & 31;
    const int warp = tid >> 5;
    const int t    = warp & 3;
    const int bbase = (warp >> 2) * 8;      // 8 rows per warp

    // Load nte for BB rows (contiguous 8 KB, float4)
    {
        const float4* s4 = (const float4*)(g_agg + (size_t)b0 * T * U);
        float4* d4 = (float4*)&nte_s[0][0];
        #pragma unroll
        for (int i = tid; i < BB * T * U / 4; i += 256) d4[i] = s4[i];
    }
    __syncthreads();

    // Stage A: score[bb][t] = sum_a tanh(sum_u nte*ws1)[a] * ws2[a]
    // ws1 column packed into f32x2 pairs over u; nte read as float4.
    {
        ull w1p[U / 2];
        #pragma unroll
        for (int u = 0; u < U; u += 2) {
            float a0 = __ldg(&ws1[(t * U + u) * A + lane]);
            float a1 = __ldg(&ws1[(t * U + u + 1) * A + lane]);
            asm("mov.b64 %0, {%1, %2};" : "=l"(w1p[u >> 1]) : "f"(a0), "f"(a1));
        }
        const float w2r = __ldg(&ws2[t * A + lane]);

        #pragma unroll
        for (int i = 0; i < 8; i++) {
            const int bb = bbase + i;
            ull acc0 = 0, acc1 = 0;  // two f32x2 accumulators
            const float4* n4 = (const float4*)&nte_s[bb][t * U];
            #pragma unroll
            for (int q = 0; q < U / 4; q++) {
                float4 nv = n4[q];
                ull nlo, nhi;
                asm("mov.b64 %0, {%1, %2};" : "=l"(nlo) : "f"(nv.x), "f"(nv.y));
                asm("mov.b64 %0, {%1, %2};" : "=l"(nhi) : "f"(nv.z), "f"(nv.w));
                FMA_F32X2(acc0, nlo, w1p[2 * q], acc0);
                FMA_F32X2(acc1, nhi, w1p[2 * q + 1], acc1);
            }
            float x0, x1, y0, y1;
            asm("mov.b64 {%0, %1}, %2;" : "=f"(x0), "=f"(x1) : "l"(acc0));
            asm("mov.b64 {%0, %1}, %2;" : "=f"(y0), "=f"(y1) : "l"(acc1));
            float sc = tanhf(x0 + x1 + y0 + y1) * w2r;
            #pragma unroll
            for (int o = 16; o; o >>= 1) sc += __shfl_xor_sync(0xFFFFFFFFu, sc, o);
            if (lane == 0) scores_s[bb][t] = sc;
        }
    }
    __syncthreads();

    // Softmax over T=4 (one thread per batch row)
    if (tid < BB) {
        float s0 = scores_s[tid][0], s1 = scores_s[tid][1];
        float s2 = scores_s[tid][2], s3 = scores_s[tid][3];
        float m = fmaxf(fmaxf(s0, s1), fmaxf(s2, s3));
        float e0 = __expf(s0 - m), e1 = __expf(s1 - m);
        float e2 = __expf(s2 - m), e3 = __expf(s3 - m);
        float inv = 1.f / (e0 + e1 + e2 + e3);
        att_s[tid][0] = e0 * inv; att_s[tid][1] = e1 * inv;
        att_s[tid][2] = e2 * inv; att_s[tid][3] = e3 * inv;
    }
    __syncthreads();

    // combined[bb][u] = sum_t att[bb][t] * nte[bb][t][u]
    #pragma unroll
    for (int i = tid; i < BB * U; i += 256) {
        const int bb = i >> 5, u = i & 31;
        float c = 0.f;
        #pragma unroll
        for (int tt = 0; tt < T; tt++) c += att_s[bb][tt] * nte_s[bb][tt * U + u];
        comb_s[bb][u] = c;
    }
    __syncthreads();

    // Stage B: out[b,t,:] = normalize(node_emb[out_nodes[b],:] + combined[b] @ w[t])
    // lane owns one float4 (= 2 f32x2) slice of D. acc = 16 u64 regs.
    ull acc[8][2];
    #pragma unroll
    for (int i = 0; i < 8; i++) { acc[i][0] = 0; acc[i][1] = 0; }

    const float4* wbase = (const float4*)w + (size_t)t * U * (D / 4) + lane;
    #pragma unroll
    for (int uc = 0; uc < U; uc += 4) {
        ull wlo[4], whi[4];
        #pragma unroll
        for (int j = 0; j < 4; j++) {
            float4 wv = __ldg(&wbase[(uc + j) * (D / 4)]);
            asm("mov.b64 %0, {%1, %2};" : "=l"(wlo[j]) : "f"(wv.x), "f"(wv.y));
            asm("mov.b64 %0, {%1, %2};" : "=l"(whi[j]) : "f"(wv.z), "f"(wv.w));
        }
        #pragma unroll
        for (int i = 0; i < 8; i++) {
            const int bb = bbase + i;
            const float4 cb = ((const float4*)&comb_s[bb][0])[uc >> 2];  // LDS.128
            ull c2;
            PACK_DUP_F32X2(c2, cb.x);
            FMA_F32X2(acc[i][0], c2, wlo[0], acc[i][0]);
            FMA_F32X2(acc[i][1], c2, whi[0], acc[i][1]);
            PACK_DUP_F32X2(c2, cb.y);
            FMA_F32X2(acc[i][0], c2, wlo[1], acc[i][0]);
            FMA_F32X2(acc[i][1], c2, whi[1], acc[i][1]);
            PACK_DUP_F32X2(c2, cb.z);
            FMA_F32X2(acc[i][0], c2, wlo[2], acc[i][0]);
            FMA_F32X2(acc[i][1], c2, whi[2], acc[i][1]);
            PACK_DUP_F32X2(c2, cb.w);
            FMA_F32X2(acc[i][0], c2, wlo[3], acc[i][0]);
            FMA_F32X2(acc[i][1], c2, whi[3], acc[i][1]);
        }
    }

    #pragma unroll
    for (int i = 0; i < 8; i++) {
        const int bb = bbase + i;
        const int b  = b0 + bb;

        float4 o;
        asm("mov.b64 {%0, %1}, %2;" : "=f"(o.x), "=f"(o.y) : "l"(acc[i][0]));
        asm("mov.b64 {%0, %1}, %2;" : "=f"(o.z), "=f"(o.w) : "l"(acc[i][1]));

        const int nidx = __ldg(&out_nodes[b]);
        const float4 nv = __ldg((const float4*)node_emb + (size_t)nidx * (D / 4) + lane);
        o.x += nv.x; o.y += nv.y; o.z += nv.z; o.w += nv.w;

        float ss = o.x * o.x + o.y * o.y + o.z * o.z + o.w * o.w;
        #pragma unroll
        for (int off = 16; off; off >>= 1) ss += __shfl_xor_sync(0xFFFFFFFFu, ss, off);

        const float scale = 1.f / fmaxf(sqrtf(ss), 1e-12f);
        o.x *= scale; o.y *= scale; o.z *= scale; o.w *= scale;

        ((float4*)out)[(size_t)(b * T + t) * (D / 4) + lane] = o;
    }
}

// ---------------------------------------------------------------------------
// Launch
// ---------------------------------------------------------------------------
extern "C" void kernel_launch(void* const* d_in, const int* in_sizes, int n_in,
                              void* d_out, int out_size) {
    const float* node_emb     = (const float*)d_in[0];  // [500000][128]
    const float* nte_tab      = (const float*)d_in[1];  // [500000][4][32]
    const float* trans_w      = (const float*)d_in[2];  // [4][32][128]
    const float* trans_w_s1   = (const float*)d_in[3];  // [4][32][32]
    const float* trans_w_s2   = (const float*)d_in[4];  // [4][32][1]
    const int*   input_nodes  = (const int*)d_in[5];    // [65536]
    const int*   output_nodes = (const int*)d_in[6];    // [8192]
    const int*   edge_src     = (const int*)d_in[7];    // [4][262144]
    const int*   edge_dst     = (const int*)d_in[8];    // [4][262144]
    float*       out          = (float*)d_out;          // [8192][4][128]

    // Zero accumulator as a graph memset node.
    void* agg_ptr = nullptr;
    cudaGetSymbolAddress(&agg_ptr, g_agg);
    cudaMemsetAsync(agg_ptr, 0, (size_t)B * T * U * sizeof(float));

    dim3 grid_e(E / 64, T);
    edge_agg_kernel<<<grid_e, 256>>>(nte_tab, input_nodes, edge_src, edge_dst);

    finalize_kernel<<<B / BB, 256>>>(node_emb, trans_w, trans_w_s1, trans_w_s2,
                                     output_nodes, out);
}